// round 2
// baseline (speedup 1.0000x reference)
#include <cuda_runtime.h>
#include <cstdint>
#include <math.h>

#define NTOK 16384
#define DIM  256
#define NEMB 16384
#define TM 128
#define TN 256
#define KC 16
#define ZP 130
#define EP 257

// ---- scratch (no allocations allowed) ----
__device__ float g_zf[NTOK * DIM];
__device__ float g_A[NTOK];
__device__ float g_B[NEMB];
__device__ unsigned long long g_best[NTOK];
__device__ int g_cnt[NEMB];
__device__ double g_part[4096];

// ---- helpers ----
__device__ __forceinline__ void fma2(unsigned long long& acc, unsigned long long a,
                                     unsigned long long b) {
    asm("fma.rn.f32x2 %0, %1, %2, %0;" : "+l"(acc) : "l"(a), "l"(b));
}
__device__ __forceinline__ unsigned long long dup2(float x) {
    unsigned long long r;
    asm("mov.b64 %0, {%1, %1};" : "=l"(r) : "r"(__float_as_uint(x)));
    return r;
}
__device__ __forceinline__ void unpack2(unsigned long long v, float& lo, float& hi) {
    unsigned a, b;
    asm("mov.b64 {%0, %1}, %2;" : "=r"(a), "=r"(b) : "l"(v));
    lo = __uint_as_float(a); hi = __uint_as_float(b);
}

__global__ void k_init() {
    int i = blockIdx.x * blockDim.x + threadIdx.x;
    if (i < NTOK) g_best[i] = 0xFFFFFFFFFFFFFFFFull;
    if (i < NEMB) g_cnt[i] = 0;
}

// z (16,256,32,32) -> g_zf (16384 tokens, 256)
__global__ void k_transpose(const float* __restrict__ z) {
    __shared__ float tile[32][33];
    int b = blockIdx.z, c0 = blockIdx.y * 32, p0 = blockIdx.x * 32;
    int tx = threadIdx.x, ty = threadIdx.y;
    tile[ty][tx] = z[((size_t)(b * 256 + c0 + ty)) * 1024 + p0 + tx];
    __syncthreads();
    g_zf[((size_t)(b * 1024 + p0 + ty)) * DIM + c0 + tx] = tile[tx][ty];
}

__global__ void k_normA() {
    int n = blockIdx.x * blockDim.x + threadIdx.x;
    if (n >= NTOK) return;
    const float* r = &g_zf[(size_t)n * DIM];
    double s = 0.0;
    for (int c = 0; c < DIM; ++c) { double v = (double)r[c]; s += v * v; }
    g_A[n] = (float)s;
}
__global__ void k_normB(const float* __restrict__ e) {
    int j = blockIdx.x * blockDim.x + threadIdx.x;
    if (j >= NEMB) return;
    const float* r = &e[(size_t)j * DIM];
    double s = 0.0;
    for (int c = 0; c < DIM; ++c) { double v = (double)r[c]; s += v * v; }
    g_B[j] = (float)s;
}

// fused distance + argmin: block = 256 thr, tile TM x TN, thread = 8 tok x 16 codes
extern "C" __global__ void __launch_bounds__(256, 1)
k_argmin(const float* __restrict__ emb) {
    __shared__ float zs[KC * ZP];
    __shared__ float es[KC * EP];
    __shared__ float Bs[TN];
    __shared__ float As[TM];

    int tid = threadIdx.x;
    int tx = tid & 15, ty = tid >> 4;
    int tok0 = blockIdx.x * TM;
    int cb = blockIdx.y * TN;

    if (tid < TM) As[tid] = g_A[tok0 + tid];
    Bs[tid] = g_B[cb + tid];

    unsigned long long acc[16][4];
#pragma unroll
    for (int q = 0; q < 16; ++q)
#pragma unroll
        for (int i = 0; i < 4; ++i) acc[q][i] = 0ull;

    for (int kb = 0; kb < DIM; kb += KC) {
        __syncthreads();
        // stage z tile (k-major): TM*KC floats = 512 float4
        for (int v = tid; v < TM * KC / 4; v += 256) {
            int t = v >> 2, k4 = v & 3;
            float4 q = *reinterpret_cast<const float4*>(&g_zf[(size_t)(tok0 + t) * DIM + kb + 4 * k4]);
            zs[(4 * k4 + 0) * ZP + t] = q.x;
            zs[(4 * k4 + 1) * ZP + t] = q.y;
            zs[(4 * k4 + 2) * ZP + t] = q.z;
            zs[(4 * k4 + 3) * ZP + t] = q.w;
        }
        // stage e tile (k-major): TN*KC floats = 1024 float4
        for (int v = tid; v < TN * KC / 4; v += 256) {
            int r = v >> 2, k4 = v & 3;
            float4 q = *reinterpret_cast<const float4*>(&emb[(size_t)(cb + r) * DIM + kb + 4 * k4]);
            es[(4 * k4 + 0) * EP + r] = q.x;
            es[(4 * k4 + 1) * EP + r] = q.y;
            es[(4 * k4 + 2) * EP + r] = q.z;
            es[(4 * k4 + 3) * EP + r] = q.w;
        }
        __syncthreads();
#pragma unroll
        for (int kk = 0; kk < KC; ++kk) {
            const float* zr = &zs[kk * ZP + 2 * ty];
            unsigned long long zp[4];
#pragma unroll
            for (int i = 0; i < 4; ++i)
                zp[i] = *reinterpret_cast<const unsigned long long*>(zr + 32 * i);
            const float* er = &es[kk * EP + tx];
#pragma unroll
            for (int q = 0; q < 16; ++q) {
                unsigned long long ev = dup2(er[16 * q]);
#pragma unroll
                for (int i = 0; i < 4; ++i) fma2(acc[q][i], zp[i], ev);
            }
        }
    }

    // finalize: d = fl(fl(A+B) - fl(2*dot)), lowest-index tie-break (q ascending)
    float a[8];
#pragma unroll
    for (int s = 0; s < 8; ++s) a[s] = As[32 * (s >> 1) + 2 * ty + (s & 1)];
    float bd[8]; unsigned bj[8];
#pragma unroll
    for (int s = 0; s < 8; ++s) { bd[s] = 3.4e38f; bj[s] = 0u; }

#pragma unroll
    for (int q = 0; q < 16; ++q) {
        unsigned j = (unsigned)(cb + 16 * q + tx);
        float Bj = Bs[16 * q + tx];
#pragma unroll
        for (int i = 0; i < 4; ++i) {
            float lo, hi;
            unpack2(acc[q][i], lo, hi);
            float d0 = __fadd_rn(__fadd_rn(a[2 * i], Bj), -__fmul_rn(2.0f, lo));
            if (d0 < bd[2 * i]) { bd[2 * i] = d0; bj[2 * i] = j; }
            float d1 = __fadd_rn(__fadd_rn(a[2 * i + 1], Bj), -__fmul_rn(2.0f, hi));
            if (d1 < bd[2 * i + 1]) { bd[2 * i + 1] = d1; bj[2 * i + 1] = j; }
        }
    }

    __syncthreads();
    unsigned long long* cand = reinterpret_cast<unsigned long long*>(es);
#pragma unroll
    for (int s = 0; s < 8; ++s) {
        int tl = 32 * (s >> 1) + 2 * ty + (s & 1);
        cand[tl * 16 + tx] = ((unsigned long long)__float_as_uint(bd[s]) << 32) | bj[s];
    }
    __syncthreads();
    if (tid < TM) {
        unsigned long long m = cand[tid * 16];
#pragma unroll
        for (int k = 1; k < 16; ++k) {
            unsigned long long v = cand[tid * 16 + k];
            if (v < m) m = v;
        }
        atomicMin(&g_best[tok0 + tid], m);
    }
}

// per-token outputs: idx, one-hot, counts
__global__ void k_idx(float* __restrict__ out_idx, float* __restrict__ out_enc) {
    int n = blockIdx.x * blockDim.x + threadIdx.x;
    if (n >= NTOK) return;
    int idx = (int)(g_best[n] & 0xFFFFFFFFull);
    out_idx[n] = (float)idx;
    out_enc[(size_t)n * NEMB + idx] = 1.0f;
    atomicAdd(&g_cnt[idx], 1);
}

// z_q straight-through output + loss partials (deterministic)
__global__ void k_finalize(const float* __restrict__ emb, float* __restrict__ out_zq) {
    __shared__ double red[1024];
    int g = blockIdx.x * 1024 + threadIdx.x;   // g = (b*256+c)*1024 + p  (output order)
    int b = g >> 18, c = (g >> 10) & 255, p = g & 1023;
    int n = b * 1024 + p;
    int idx = (int)(g_best[n] & 0xFFFFFFFFull);
    float zq = emb[(size_t)idx * DIM + c];
    float zp = g_zf[(size_t)n * DIM + c];
    float diff = __fsub_rn(zq, zp);
    out_zq[g] = __fadd_rn(zp, diff);           // straight-through rounding, matches ref
    float sq = __fmul_rn(diff, diff);
    red[threadIdx.x] = (double)sq;
    __syncthreads();
    for (int s = 512; s > 0; s >>= 1) {
        if (threadIdx.x < s) red[threadIdx.x] += red[threadIdx.x + s];
        __syncthreads();
    }
    if (threadIdx.x == 0) g_part[blockIdx.x] = red[0];
}

// scalars: loss + perplexity (single block, fixed order)
__global__ void k_scalars(float* __restrict__ out_loss, float* __restrict__ out_perp) {
    __shared__ double red[1024];
    int t = threadIdx.x;
    double s = 0.0;
    for (int i = t; i < 4096; i += 1024) s += g_part[i];
    red[t] = s;
    __syncthreads();
    for (int w = 512; w > 0; w >>= 1) {
        if (t < w) red[t] += red[t + w];
        __syncthreads();
    }
    double total = red[0];
    __syncthreads();
    double ent = 0.0;
    for (int j = t; j < NEMB; j += 1024) {
        double e = (double)g_cnt[j] / (double)NTOK;
        ent += e * log(e + 1e-10);
    }
    red[t] = ent;
    __syncthreads();
    for (int w = 512; w > 0; w >>= 1) {
        if (t < w) red[t] += red[t + w];
        __syncthreads();
    }
    if (t == 0) {
        double m = total / (double)(NTOK * DIM);
        *out_loss = (float)(m + 0.25 * m);
        *out_perp = (float)exp(-red[0]);
    }
}

extern "C" void kernel_launch(void* const* d_in, const int* in_sizes, int n_in,
                              void* d_out, int out_size) {
    const float* z = (const float*)d_in[0];
    const float* emb = (const float*)d_in[1];
    float* out = (float*)d_out;

    const size_t ZQ_OFF = 0;
    const size_t LOSS_OFF = 4194304;
    const size_t PERP_OFF = 4194305;
    const size_t ENC_OFF = 4194306;
    const size_t IDX_OFF = ENC_OFF + (size_t)NTOK * NEMB;   // 272629762

    cudaMemsetAsync(out + ENC_OFF, 0, (size_t)NTOK * NEMB * sizeof(float));
    k_init<<<64, 256>>>();
    {
        dim3 grid(32, 8, 16), blk(32, 32);
        k_transpose<<<grid, blk>>>(z);
    }
    k_normA<<<64, 256>>>();
    k_normB<<<64, 256>>>(emb);
    {
        dim3 grid(NTOK / TM, NEMB / TN);
        k_argmin<<<grid, 256>>>(emb);
    }
    k_idx<<<64, 256>>>(out + IDX_OFF, out + ENC_OFF);
    k_finalize<<<4096, 1024>>>(emb, out + ZQ_OFF);
    k_scalars<<<1, 1024>>>(out + LOSS_OFF, out + PERP_OFF);
    (void)in_sizes; (void)n_in; (void)out_size;
}

// round 4
// speedup vs baseline: 2.8481x; 2.8481x over previous
#include <cuda_runtime.h>
#include <cuda_bf16.h>
#include <cstdint>
#include <math.h>

#define NTOK 16384
#define DIM  256
#define NEMB 16384
#define TM 128
#define TN 128
#define NSTEP 16          // 256 / 16
#define PITCH 48          // bytes per tile row (16 k-dims * 2B, padded 32->48 for bank-free ldmatrix)
#define TILE_B (128 * PITCH)          // 6144
#define STAGE_B (4 * TILE_B)          // 24576 (zh, zl, eh, el)
#define SMEM_TOTAL (2 * STAGE_B)      // 49152

// ---- scratch (no allocations allowed) ----
__device__ float g_zf[NTOK * DIM];
__device__ __align__(16) __nv_bfloat16 g_zh[NTOK * DIM];
__device__ __align__(16) __nv_bfloat16 g_zl[NTOK * DIM];
__device__ __align__(16) __nv_bfloat16 g_eh[NEMB * DIM];
__device__ __align__(16) __nv_bfloat16 g_el[NEMB * DIM];
__device__ float g_A[NTOK];
__device__ float g_B[NEMB];
__device__ unsigned long long g_best[NTOK];
__device__ int g_cnt[NEMB];
__device__ double g_part[4096];

// ---- asm helpers ----
__device__ __forceinline__ uint32_t smem_u32(const void* p) {
    uint32_t a;
    asm("{ .reg .u64 t; cvta.to.shared.u64 t, %1; cvt.u32.u64 %0, t; }" : "=r"(a) : "l"(p));
    return a;
}
#define LDSM4(r, addr) \
    asm volatile("ldmatrix.sync.aligned.m8n8.x4.shared.b16 {%0,%1,%2,%3}, [%4];" \
        : "=r"((r)[0]), "=r"((r)[1]), "=r"((r)[2]), "=r"((r)[3]) : "r"(addr))
#define MMA_BF16(c, a, b0, b1) \
    asm volatile("mma.sync.aligned.m16n8k16.row.col.f32.bf16.bf16.f32 " \
        "{%0,%1,%2,%3}, {%4,%5,%6,%7}, {%8,%9}, {%0,%1,%2,%3};" \
        : "+f"((c)[0]), "+f"((c)[1]), "+f"((c)[2]), "+f"((c)[3]) \
        : "r"((a)[0]), "r"((a)[1]), "r"((a)[2]), "r"((a)[3]), "r"(b0), "r"(b1))

// ---------------- prep kernels ----------------
__global__ void k_init() {
    int i = blockIdx.x * blockDim.x + threadIdx.x;
    if (i < NTOK) g_best[i] = 0xFFFFFFFFFFFFFFFFull;
    if (i < NEMB) g_cnt[i] = 0;
}

// z (16,256,32,32) -> token-major fp32 + bf16 hi/lo split
__global__ void k_prep_z(const float* __restrict__ z) {
    __shared__ float tile[32][33];
    int b = blockIdx.z, c0 = blockIdx.y * 32, p0 = blockIdx.x * 32;
    int tx = threadIdx.x, ty = threadIdx.y;
    tile[ty][tx] = z[((size_t)(b * 256 + c0 + ty)) * 1024 + p0 + tx];
    __syncthreads();
    float v = tile[tx][ty];
    size_t idx = ((size_t)(b * 1024 + p0 + ty)) * DIM + c0 + tx;
    g_zf[idx] = v;
    __nv_bfloat16 h = __float2bfloat16(v);
    g_zh[idx] = h;
    g_zl[idx] = __float2bfloat16(v - __bfloat162float(h));
}

// embedding -> bf16 hi/lo split + row norms (warp per row)
__global__ void k_prep_e(const float* __restrict__ e) {
    int wid = threadIdx.x >> 5, lid = threadIdx.x & 31;
    int r = blockIdx.x * 8 + wid;
    const float* row = e + (size_t)r * DIM;
    double s = 0.0;
#pragma unroll
    for (int i = 0; i < 8; ++i) {
        int c = i * 32 + lid;
        float v = row[c];
        __nv_bfloat16 h = __float2bfloat16(v);
        g_eh[(size_t)r * DIM + c] = h;
        g_el[(size_t)r * DIM + c] = __float2bfloat16(v - __bfloat162float(h));
        s += (double)v * (double)v;
    }
#pragma unroll
    for (int o = 16; o; o >>= 1) s += __shfl_down_sync(0xffffffffu, s, o);
    if (lid == 0) g_B[r] = (float)s;
}

__global__ void k_normA() {
    int wid = threadIdx.x >> 5, lid = threadIdx.x & 31;
    int r = blockIdx.x * 8 + wid;
    const float* row = g_zf + (size_t)r * DIM;
    double s = 0.0;
#pragma unroll
    for (int i = 0; i < 8; ++i) {
        float v = row[i * 32 + lid];
        s += (double)v * (double)v;
    }
#pragma unroll
    for (int o = 16; o; o >>= 1) s += __shfl_down_sync(0xffffffffu, s, o);
    if (lid == 0) g_A[r] = (float)s;
}

// ---------------- HMMA bf16-split distance + argmin ----------------
// grid (128 token-tiles, 128 code-tiles), 256 thr, warp grid 2x4, warp tile 64x32.
extern "C" __global__ void __launch_bounds__(256, 1)
k_argmin() {
    extern __shared__ char smem[];
    uint32_t sb = smem_u32(smem);
    int tid = threadIdx.x;
    int l = tid & 31, wid = tid >> 5;
    int wr = wid >> 2, wc = wid & 3;
    int tok0 = blockIdx.x * TM, cb = blockIdx.y * TN;

    float acc[4][4][4];
#pragma unroll
    for (int mt = 0; mt < 4; ++mt)
#pragma unroll
        for (int nt = 0; nt < 4; ++nt)
#pragma unroll
            for (int f = 0; f < 4; ++f) acc[mt][nt][f] = 0.0f;

    // staging: thread -> (row, 16B-part)
    int srow = tid >> 1, part = tid & 1;
    const uint4* srcZh = reinterpret_cast<const uint4*>(&g_zh[(size_t)(tok0 + srow) * DIM]);
    const uint4* srcZl = reinterpret_cast<const uint4*>(&g_zl[(size_t)(tok0 + srow) * DIM]);
    const uint4* srcEh = reinterpret_cast<const uint4*>(&g_eh[(size_t)(cb + srow) * DIM]);
    const uint4* srcEl = reinterpret_cast<const uint4*>(&g_el[(size_t)(cb + srow) * DIM]);
    uint32_t stoff = (uint32_t)(srow * PITCH + part * 16);

    // stage step 0
    {
        int off = part;
        uint4 a = srcZh[off], b = srcZl[off], c = srcEh[off], d = srcEl[off];
        char* base = smem;
        *reinterpret_cast<uint4*>(base + 0 * TILE_B + stoff) = a;
        *reinterpret_cast<uint4*>(base + 1 * TILE_B + stoff) = b;
        *reinterpret_cast<uint4*>(base + 2 * TILE_B + stoff) = c;
        *reinterpret_cast<uint4*>(base + 3 * TILE_B + stoff) = d;
    }
    __syncthreads();

    // ldmatrix lane offsets
    uint32_t a_off = (uint32_t)((wr * 64 + (l & 15)) * PITCH + (l >> 4) * 16);
    uint32_t b_off = (uint32_t)((wc * 32 + (l & 7) + ((l >> 4) << 3)) * PITCH + ((l >> 3) & 1) * 16);

    for (int ks = 0; ks < NSTEP; ++ks) {
        int cur = ks & 1;
        uint4 ra, rb, rc, rd;
        if (ks < NSTEP - 1) {
            int off = ((ks + 1) << 1) + part;
            ra = srcZh[off]; rb = srcZl[off]; rc = srcEh[off]; rd = srcEl[off];
        }
        uint32_t sbase = sb + (uint32_t)(cur * STAGE_B);

        uint32_t Ah[4][4], Al[4][4];
#pragma unroll
        for (int mt = 0; mt < 4; ++mt) {
            uint32_t ad = sbase + (uint32_t)(mt * 16 * PITCH) + a_off;
            LDSM4(Ah[mt], ad);
            LDSM4(Al[mt], ad + TILE_B);
        }
        uint32_t Bh[2][4], Bl[2][4];
#pragma unroll
        for (int pr = 0; pr < 2; ++pr) {
            uint32_t bd = sbase + (uint32_t)(2 * TILE_B + pr * 16 * PITCH) + b_off;
            LDSM4(Bh[pr], bd);
            LDSM4(Bl[pr], bd + TILE_B);
        }
#pragma unroll
        for (int mt = 0; mt < 4; ++mt)
#pragma unroll
            for (int nt = 0; nt < 4; ++nt) {
                int pr = nt >> 1, lo = (nt & 1) * 2;
                MMA_BF16(acc[mt][nt], Ah[mt], Bh[pr][lo], Bh[pr][lo + 1]);   // zh*eh
                MMA_BF16(acc[mt][nt], Ah[mt], Bl[pr][lo], Bl[pr][lo + 1]);   // zh*el
                MMA_BF16(acc[mt][nt], Al[mt], Bh[pr][lo], Bh[pr][lo + 1]);   // zl*eh
            }

        if (ks < NSTEP - 1) {
            __syncthreads();
            char* base = smem + (1 - cur) * STAGE_B;
            *reinterpret_cast<uint4*>(base + 0 * TILE_B + stoff) = ra;
            *reinterpret_cast<uint4*>(base + 1 * TILE_B + stoff) = rb;
            *reinterpret_cast<uint4*>(base + 2 * TILE_B + stoff) = rc;
            *reinterpret_cast<uint4*>(base + 3 * TILE_B + stoff) = rd;
            __syncthreads();
        }
    }

    // epilogue: d = fl(fl(A+B) - fl(dot+dot)), packed argmin w/ lowest-index tie-break
    __syncthreads();
    unsigned long long* cand = reinterpret_cast<unsigned long long*>(smem);
    if (tid < TM) cand[tid] = 0xFFFFFFFFFFFFFFFFull;
    __syncthreads();

#pragma unroll
    for (int mt = 0; mt < 4; ++mt)
#pragma unroll
        for (int fr = 0; fr < 2; ++fr) {
            int trow = wr * 64 + mt * 16 + (l >> 2) + fr * 8;
            float Aval = g_A[tok0 + trow];
            unsigned long long best = 0xFFFFFFFFFFFFFFFFull;
#pragma unroll
            for (int nt = 0; nt < 4; ++nt)
#pragma unroll
                for (int fc = 0; fc < 2; ++fc) {
                    int code = cb + wc * 32 + nt * 8 + 2 * (l & 3) + fc;
                    float dot = acc[mt][nt][fr * 2 + fc];
                    float d = __fadd_rn(__fadd_rn(Aval, g_B[code]),
                                        -__fadd_rn(dot, dot));
                    unsigned long long p =
                        ((unsigned long long)__float_as_uint(d) << 32) | (unsigned)code;
                    if (p < best) best = p;
                }
            unsigned long long o;
            o = __shfl_xor_sync(0xffffffffu, best, 1); if (o < best) best = o;
            o = __shfl_xor_sync(0xffffffffu, best, 2); if (o < best) best = o;
            if ((l & 3) == 0) atomicMin(&cand[trow], best);
        }
    __syncthreads();
    if (tid < TM) atomicMin(&g_best[tok0 + tid], cand[tid]);
}

// ---------------- outputs ----------------
__global__ void k_idx(float* __restrict__ out_idx, float* __restrict__ out_enc) {
    int n = blockIdx.x * blockDim.x + threadIdx.x;
    if (n >= NTOK) return;
    int idx = (int)(g_best[n] & 0xFFFFFFFFull);
    out_idx[n] = (float)idx;
    out_enc[(size_t)n * NEMB + idx] = 1.0f;
    atomicAdd(&g_cnt[idx], 1);
}

__global__ void k_finalize(const float* __restrict__ emb, float* __restrict__ out_zq) {
    __shared__ double red[1024];
    int g = blockIdx.x * 1024 + threadIdx.x;
    int b = g >> 18, c = (g >> 10) & 255, p = g & 1023;
    int n = b * 1024 + p;
    int idx = (int)(g_best[n] & 0xFFFFFFFFull);
    float zq = emb[(size_t)idx * DIM + c];
    float zp = g_zf[(size_t)n * DIM + c];
    float diff = __fsub_rn(zq, zp);
    out_zq[g] = __fadd_rn(zp, diff);
    red[threadIdx.x] = (double)__fmul_rn(diff, diff);
    __syncthreads();
    for (int s = 512; s > 0; s >>= 1) {
        if (threadIdx.x < s) red[threadIdx.x] += red[threadIdx.x + s];
        __syncthreads();
    }
    if (threadIdx.x == 0) g_part[blockIdx.x] = red[0];
}

__global__ void k_scalars(float* __restrict__ out_loss, float* __restrict__ out_perp) {
    __shared__ double red[1024];
    int t = threadIdx.x;
    double s = 0.0;
    for (int i = t; i < 4096; i += 1024) s += g_part[i];
    red[t] = s;
    __syncthreads();
    for (int w = 512; w > 0; w >>= 1) {
        if (t < w) red[t] += red[t + w];
        __syncthreads();
    }
    double total = red[0];
    __syncthreads();
    double ent = 0.0;
    for (int j = t; j < NEMB; j += 1024) {
        double e = (double)g_cnt[j] / (double)NTOK;
        ent += e * log(e + 1e-10);
    }
    red[t] = ent;
    __syncthreads();
    for (int w = 512; w > 0; w >>= 1) {
        if (t < w) red[t] += red[t + w];
        __syncthreads();
    }
    if (t == 0) {
        double m = total / (double)(NTOK * DIM);
        *out_loss = (float)(m + 0.25 * m);
        *out_perp = (float)exp(-red[0]);
    }
}

extern "C" void kernel_launch(void* const* d_in, const int* in_sizes, int n_in,
                              void* d_out, int out_size) {
    const float* z = (const float*)d_in[0];
    const float* emb = (const float*)d_in[1];
    float* out = (float*)d_out;

    const size_t ZQ_OFF = 0;
    const size_t LOSS_OFF = 4194304;
    const size_t PERP_OFF = 4194305;
    const size_t ENC_OFF = 4194306;
    const size_t IDX_OFF = ENC_OFF + (size_t)NTOK * NEMB;

    cudaFuncSetAttribute(k_argmin, cudaFuncAttributeMaxDynamicSharedMemorySize, SMEM_TOTAL);

    cudaMemsetAsync(out + ENC_OFF, 0, (size_t)NTOK * NEMB * sizeof(float));
    k_init<<<64, 256>>>();
    {
        dim3 grid(32, 8, 16), blk(32, 32);
        k_prep_z<<<grid, blk>>>(z);
    }
    k_prep_e<<<2048, 256>>>(emb);
    k_normA<<<2048, 256>>>();
    {
        dim3 grid(NTOK / TM, NEMB / TN);
        k_argmin<<<grid, 256, SMEM_TOTAL>>>();
    }
    k_idx<<<64, 256>>>(out + IDX_OFF, out + ENC_OFF);
    k_finalize<<<4096, 1024>>>(emb, out + ZQ_OFF);
    k_scalars<<<1, 1024>>>(out + LOSS_OFF, out + PERP_OFF);
    (void)in_sizes; (void)n_in; (void)out_size;
}